// round 1
// baseline (speedup 1.0000x reference)
#include <cuda_runtime.h>
#include <cuda_bf16.h>

// Cascaded FIR: v[i] = (i>=F) ? x[i] + sum_{j<F} h[j]*x[i-1-j] : 0
//               y[i] = (i>=F) ? v[i] + sum_{j<F} h[F-1-j]*v[i-1-j] : 0
// Note: y[i] = v[i] + sum_{m<F} h[m]*v[i-16+m]   (m = F-1-j)
//
// B=256 rows, N=131072 cols, F=16.

#define F       16
#define THREADS 256
#define RPT     8
#define TILE    (THREADS * RPT)   // 2048
#define NCOL    131072
#define NROW    256

__global__ __launch_bounds__(THREADS)
void fir2_kernel(const float* __restrict__ x,
                 const float* __restrict__ h,
                 float* __restrict__ y)
{
    // sx[k] = x[t0 - 32 + k],  k in [0, TILE+32)
    // sv[k] = v[t0 - 16 + k],  k in [0, TILE+16)
    __shared__ float sx[TILE + 2 * F];
    __shared__ float sv[TILE + F];

    const int tid = threadIdx.x;
    const int row = blockIdx.y;
    const int t0  = blockIdx.x * TILE;
    const size_t rowoff = (size_t)row * NCOL;
    const float* xr = x + rowoff;

    // Filter taps (uniform across threads).
    float hh[F];
#pragma unroll
    for (int j = 0; j < F; j++) hh[j] = __ldg(h + j);

    // Cooperative coalesced load of x tile + 32-left-halo (zero-fill past row start).
    const int gbase = t0 - 2 * F;
    for (int k = tid; k < TILE + 2 * F; k += THREADS) {
        const int col = gbase + k;
        sx[k] = (col >= 0) ? xr[col] : 0.0f;
    }
    __syncthreads();

    // ---------------- Phase 1: v into SMEM (each element computed once) ------
    // Main region: thread computes v at global i = t0 + tid*RPT + r, r in [0,RPT).
    // Register window: w[c] = sx[tid*RPT + F + c] = x[t0 + tid*RPT - 16 + c], c in [0, RPT+F).
    {
        float w[RPT + F];
        const int bx = tid * RPT + F;   // float4-aligned (8*tid + 16)
#pragma unroll
        for (int q = 0; q < (RPT + F) / 4; q++)
            *reinterpret_cast<float4*>(&w[q * 4]) =
                *reinterpret_cast<const float4*>(&sx[bx + q * 4]);

#pragma unroll
        for (int r = 0; r < RPT; r++) {
            float acc = w[r + F];                 // x[i]
#pragma unroll
            for (int j = 0; j < F; j++)
                acc = fmaf(hh[j], w[r + F - 1 - j], acc);   // h[j]*x[i-1-j]
            const int gi = t0 + tid * RPT + r;
            sv[F + tid * RPT + r] = (gi >= F) ? acc : 0.0f;
        }

        // Left halo of v: threads 0..15 compute v[t0 - 16 + tid].
        if (tid < F) {
            float acc = sx[tid + F];              // x[i], i = t0-16+tid
#pragma unroll
            for (int j = 0; j < F; j++)
                acc = fmaf(hh[j], sx[tid + F - 1 - j], acc);
            const int gi = t0 - F + tid;
            sv[tid] = (gi >= F) ? acc : 0.0f;
        }
    }
    __syncthreads();

    // ---------------- Phase 2: y from SMEM v --------------------------------
    // y[i] = v[i] + sum_m hh[m] * v[i-16+m]
    // Register window: w[c] = sv[tid*RPT + c] = v[t0 + tid*RPT - 16 + c], c in [0, RPT+F).
    {
        float w[RPT + F];
        const int bv = tid * RPT;       // float4-aligned
#pragma unroll
        for (int q = 0; q < (RPT + F) / 4; q++)
            *reinterpret_cast<float4*>(&w[q * 4]) =
                *reinterpret_cast<const float4*>(&sv[bv + q * 4]);

        float out[RPT];
#pragma unroll
        for (int r = 0; r < RPT; r++) {
            float acc = w[r + F];                 // v[i]
#pragma unroll
            for (int m = 0; m < F; m++)
                acc = fmaf(hh[m], w[r + m], acc); // h[m]*v[i-16+m]
            out[r] = acc;                         // masked-v makes i<F outputs 0 already
        }

        // Coalesced-ish float4 stores (32B/lane, merged in L2).
        float4* yo = reinterpret_cast<float4*>(y + rowoff + t0 + tid * RPT);
        yo[0] = make_float4(out[0], out[1], out[2], out[3]);
        yo[1] = make_float4(out[4], out[5], out[6], out[7]);
    }
}

extern "C" void kernel_launch(void* const* d_in, const int* in_sizes, int n_in,
                              void* d_out, int out_size)
{
    const float* x = (const float*)d_in[0];   // (256, 131072) f32
    const float* h = (const float*)d_in[1];   // (1, 16) f32
    float* y = (float*)d_out;                 // (256, 131072) f32

    dim3 grid(NCOL / TILE, NROW);
    fir2_kernel<<<grid, THREADS>>>(x, h, y);
}

// round 2
// speedup vs baseline: 1.2656x; 1.2656x over previous
#include <cuda_runtime.h>
#include <cuda_bf16.h>

// Cascaded 16-tap FIR pair == single 33-tap causal conv (g = [1,h] conv [1,h_rev])
// for all columns i >= 32. Columns [0,32) fixed up exactly (v-mask aware).
//
// B=256 rows, N=131072 cols, F=16.

#define F       16
#define GT      33                 // combined taps
#define THREADS 128
#define RPT     16
#define TILE    (THREADS * RPT)    // 2048
#define HALO    32
#define NCOL    131072
#define NROW    256

__device__ float g_taps[GT];

// ---------------------------------------------------------------------------
// Kernel 1: combine the two FIR kernels into one 33-tap kernel.
// k[a]  = (a==0) ? 1 : h[a-1]          (first stage, [1, h])
// k2[b] = (b==0) ? 1 : h[16-b]         (second stage, [1, h_rev])
// g[j]  = sum_a k[a] * k2[j-a]
// ---------------------------------------------------------------------------
__global__ void compute_taps(const float* __restrict__ h)
{
    const int j = threadIdx.x;
    if (j >= GT) return;
    float acc = 0.0f;
    for (int a = 0; a <= j; a++) {
        const int b = j - a;
        if (a <= F && b <= F) {
            const float ka = (a == 0) ? 1.0f : h[a - 1];
            const float kb = (b == 0) ? 1.0f : h[F - b];
            acc += ka * kb;
        }
    }
    g_taps[j] = acc;
}

// ---------------------------------------------------------------------------
// Kernel 2: main 33-tap conv. y[i] = x[i] + sum_{j=1}^{32} g[j] * x[i-j].
// Valid for i >= 32; columns [0,32) overwritten by fixup kernel.
// ---------------------------------------------------------------------------
__global__ __launch_bounds__(THREADS, 3)
void conv33_kernel(const float* __restrict__ x, float* __restrict__ y)
{
    __shared__ float sx[TILE + HALO];     // sx[c] = x[row][t0 - 32 + c]

    const int tid = threadIdx.x;
    const int row = blockIdx.y;
    const int t0  = blockIdx.x * TILE;
    const size_t rowoff = (size_t)row * NCOL;

    // Taps -> registers (uniform; candidates for UR promotion).
    float g[GT];
#pragma unroll
    for (int j = 0; j < GT; j++) g[j] = g_taps[j];

    // Cooperative float4 load of tile + 32-left-halo (zero-fill before row start).
    {
        const float4* src = reinterpret_cast<const float4*>(x + rowoff + t0 - HALO);
        float4* dst = reinterpret_cast<float4*>(sx);
        const int nvec = (TILE + HALO) / 4;   // 520
        if (blockIdx.x == 0) {
            for (int k = tid; k < nvec; k += THREADS)
                dst[k] = (k >= HALO / 4) ? src[k] : make_float4(0.f, 0.f, 0.f, 0.f);
        } else {
#pragma unroll
            for (int k = tid; k < nvec; k += THREADS)
                dst[k] = src[k];
        }
    }
    __syncthreads();

    // Per-thread register window: w[c] = sx[tid*RPT + c] = x[t0 + tid*RPT - 32 + c]
    float w[RPT + HALO];                  // 48 floats
    const int b = tid * RPT;              // multiple of 16 -> 64B aligned in smem
#pragma unroll
    for (int q = 0; q < (RPT + HALO) / 4; q++)
        *reinterpret_cast<float4*>(&w[q * 4]) =
            *reinterpret_cast<const float4*>(&sx[b + q * 4]);

    // Output i = t0 + b + r  ->  x[i - j] = w[r + 32 - j]
    float out[RPT];
#pragma unroll
    for (int r = 0; r < RPT; r++) {
        float acc = w[r + HALO];          // g[0] = 1 (identity tap)
#pragma unroll
        for (int j = 1; j < GT; j++)
            acc = fmaf(g[j], w[r + HALO - j], acc);
        out[r] = acc;
    }

    float4* yo = reinterpret_cast<float4*>(y + rowoff + t0 + b);
#pragma unroll
    for (int q = 0; q < RPT / 4; q++)
        yo[q] = make_float4(out[q * 4], out[q * 4 + 1], out[q * 4 + 2], out[q * 4 + 3]);
}

// ---------------------------------------------------------------------------
// Kernel 3: exact masked two-stage result for columns [0, 32) of every row.
// v[k] = x[k] + sum_j h[j] x[k-1-j]  (k in [16,32));  v[k<16] := 0
// y[i] = v[i] + sum_m h[m] * v_masked[i-16+m]   for i in [16,32);  y[i<16] = 0
// One warp per row.
// ---------------------------------------------------------------------------
__global__ void fixup_kernel(const float* __restrict__ x,
                             const float* __restrict__ h,
                             float* __restrict__ y)
{
    const int row = blockIdx.x;
    const int t   = threadIdx.x;          // 0..31
    const size_t rowoff = (size_t)row * NCOL;
    const float* xr = x + rowoff;

    __shared__ float sv[F];               // v[16..31]

    if (t < F) {
        const int k = F + t;
        float acc = xr[k];
#pragma unroll
        for (int j = 0; j < F; j++)
            acc = fmaf(h[j], xr[k - 1 - j], acc);
        sv[t] = acc;
    }
    __syncwarp();

    if (t < F) {
        const int i = F + t;
        float acc = sv[i - F];            // v[i]
#pragma unroll
        for (int m = 0; m < F; m++) {
            const int k = i - F + m;      // in [0, 31)
            if (k >= F) acc = fmaf(h[m], sv[k - F], acc);
        }
        y[rowoff + i] = acc;
    } else {
        y[rowoff + (t - F)] = 0.0f;       // columns [0,16) are zero
    }
}

extern "C" void kernel_launch(void* const* d_in, const int* in_sizes, int n_in,
                              void* d_out, int out_size)
{
    const float* x = (const float*)d_in[0];   // (256, 131072) f32
    const float* h = (const float*)d_in[1];   // (1, 16) f32
    float* y = (float*)d_out;                 // (256, 131072) f32

    compute_taps<<<1, 64>>>(h);
    dim3 grid(NCOL / TILE, NROW);
    conv33_kernel<<<grid, THREADS>>>(x, y);
    fixup_kernel<<<NROW, 32>>>(x, h, y);
}